// round 2
// baseline (speedup 1.0000x reference)
#include <cuda_runtime.h>
#include <cstdint>

// ============================================================================
// LSTM_34883724378521 : T=60, C=H=128, N=4096, TOUT=114
// Portable-PTX tensor-core path (mma.sync tf32) — target compute_103 has no
// tcgen05 support, so we use HMMA fallback via mma.sync.m16n8k8.
// ============================================================================
#define NB 4096
#define HD 128
#define NG 512

// ---------------------------------------------------------------------------
// helpers
// ---------------------------------------------------------------------------
__device__ __forceinline__ uint32_t smem_u32(const void* p) {
    uint32_t a;
    asm("{ .reg .u64 t; cvta.to.shared.u64 t, %1; cvt.u32.u64 %0, t; }"
        : "=r"(a) : "l"(p));
    return a;
}
__device__ __forceinline__ void cp16(uint32_t dst, const void* src) {
    asm volatile("cp.async.ca.shared.global [%0], [%1], 16;"
                 :: "r"(dst), "l"(src));
}
#define CP_COMMIT() asm volatile("cp.async.commit_group;" ::: "memory")
#define CP_WAIT(n)  asm volatile("cp.async.wait_group %0;" :: "n"(n) : "memory")

__device__ __forceinline__ uint32_t rna_tf32(float v) {
    uint32_t u; asm("cvt.rna.tf32.f32 %0, %1;" : "=r"(u) : "f"(v)); return u;
}

__device__ __forceinline__ void mma8(float* d, const uint32_t* a, const uint32_t* b) {
    asm volatile(
        "mma.sync.aligned.m16n8k8.row.col.f32.tf32.tf32.f32 "
        "{%0,%1,%2,%3}, {%4,%5,%6,%7}, {%8,%9}, {%0,%1,%2,%3};"
        : "+f"(d[0]), "+f"(d[1]), "+f"(d[2]), "+f"(d[3])
        : "r"(a[0]), "r"(a[1]), "r"(a[2]), "r"(a[3]), "r"(b[0]), "r"(b[1]));
}

__device__ __forceinline__ float sigf(float x) {
    return 1.0f / (1.0f + __expf(-x));
}
__device__ __forceinline__ float tanhf_(float x) {
    return 1.0f - 2.0f / (__expf(2.0f * x) + 1.0f);
}

// ---------------------------------------------------------------------------
// persistent device state (no cudaMalloc allowed)
// ---------------------------------------------------------------------------
__device__ float g_Hbuf0[HD * NB];   // h state, h-major [H][N], ping
__device__ float g_Hbuf1[HD * NB];   // pong
__device__ float g_Cbuf [HD * NB];   // c state, h-major
__device__ float g_W1[NG * 256];     // permuted [4h+g][x|h], tf32-rounded
__device__ float g_W2[NG * 128];     // permuted (W_ih+W_hh), tf32-rounded
__device__ float g_bias[NG];         // permuted b_ih + b_hh

// ---------------------------------------------------------------------------
// prep: permute rows (r = 4*h + g <- g*128 + h), RNA-round weights, zero state
// ---------------------------------------------------------------------------
__global__ void prep_kernel(const float* __restrict__ Wih, const float* __restrict__ Whh,
                            const float* __restrict__ bih, const float* __restrict__ bhh) {
    int tid = blockIdx.x * 256 + threadIdx.x;       // 512*256 = 131072 threads
    int r = tid >> 8, k = tid & 255;
    int h = r >> 2, g = r & 3;
    int orig = g * HD + h;
    float v = (k < 128) ? Wih[orig * HD + k] : Whh[orig * HD + (k - 128)];
    g_W1[r * 256 + k] = __uint_as_float(rna_tf32(v));
    if (k < 128)
        g_W2[r * 128 + k] =
            __uint_as_float(rna_tf32(Wih[orig * HD + k] + Whh[orig * HD + k]));
    if (k == 0) g_bias[r] = bih[orig] + bhh[orig];
    for (int i = tid; i < HD * NB; i += 131072) {
        g_Hbuf0[i] = 0.0f;
        g_Cbuf[i]  = 0.0f;
    }
}

// ---------------------------------------------------------------------------
// smem layout (bytes)
// ---------------------------------------------------------------------------
static constexpr int A_STR = 136;                    // floats per k-row (128 + 8 pad)
static constexpr int B_STR = 36;                     // floats per gate-row (32 + 4 pad)
static constexpr int A_BUF = 32 * A_STR * 4;         // 17408
static constexpr int B_BUF = 128 * B_STR * 4;        // 18432
static constexpr int S_STR = 132;                    // stage stride (floats)
static constexpr int H_STR = 129;

static constexpr int SM_BIAS = 0;                    // 512 B
static constexpr int SM_A    = 512;                  // 2 * 17408
static constexpr int SM_B    = SM_A + 2 * A_BUF;     // 2 * 18432
static constexpr int SM_S    = SM_B + 2 * B_BUF;     // 128*132*4 = 67584
static constexpr int SM_H2   = SM_S + 128 * S_STR * 4;  // 32*129*4 = 16512
static constexpr int SM_TOT  = SM_H2 + 32 * H_STR * 4;  // ~156 KB

// ---------------------------------------------------------------------------
// fused LSTM step. CTA tile: M=128 batch rows x N=128 gate cols, K = NCH*32.
// grid = (4 gate tiles, 32 batch tiles), 256 threads.
// ---------------------------------------------------------------------------
template <int NCH>
__global__ void __launch_bounds__(256, 1)
lstm_step(const float* __restrict__ xsrc,   // [128][NB] x_t slice (phase1) or null
          const float* __restrict__ hprev,  // [128][NB]
          float* __restrict__ hnext,        // [128][NB]
          float* __restrict__ out, int t_out, int TOUT) {
    extern __shared__ char sm[];
    float* smf = (float*)sm;
    const int tid  = threadIdx.x;
    const int wid  = tid >> 5, lane = tid & 31;
    const int g    = lane >> 2, tig = lane & 3;      // mma groupID / tid-in-group
    const int j    = blockIdx.x;                     // gate tile (units [32j,32j+32))
    const int n0   = blockIdx.y * 128;               // batch rows

    if (tid < 128) smf[SM_BIAS / 4 + tid] = g_bias[j * 128 + tid];

    const float* W = (NCH == 8) ? g_W1 : g_W2;
    const int KT   = NCH * 32;
    const uint32_t sb = smem_u32(sm);

    // ---- async loaders ----
    auto load_chunk = [&](int ch, int buf) {
        const float* asrc = (NCH == 8 && ch < 4) ? xsrc : hprev;
        const int koff = (NCH == 8 && ch >= 4) ? (ch - 4) * 32 : ch * 32;
        #pragma unroll
        for (int it = 0; it < 4; it++) {
            int idx = tid + it * 256;
            {   // A: 32 k-rows x 128 m
                int kk = idx >> 5, mp = (idx & 31) << 2;
                cp16(sb + SM_A + buf * A_BUF + (kk * A_STR + mp) * 4,
                     asrc + (size_t)(koff + kk) * NB + n0 + mp);
            }
            {   // B: 128 gate rows x 32 k
                int n = idx >> 3, q = (idx & 7) << 2;
                cp16(sb + SM_B + buf * B_BUF + (n * B_STR + q) * 4,
                     W + (size_t)(j * 128 + n) * KT + ch * 32 + q);
            }
        }
        CP_COMMIT();
    };

    float acc[2][8][4];
    #pragma unroll
    for (int mt = 0; mt < 2; mt++)
        #pragma unroll
        for (int nt = 0; nt < 8; nt++)
            #pragma unroll
            for (int e = 0; e < 4; e++) acc[mt][nt][e] = 0.0f;

    const int wm = wid >> 1;            // 0..3 -> m base wm*32
    const int wn = wid & 1;             // 0..1 -> n base wn*64

    load_chunk(0, 0);
    #pragma unroll
    for (int ch = 0; ch < NCH; ch++) {
        if (ch + 1 < NCH) load_chunk(ch + 1, (ch + 1) & 1);
        if (ch + 1 < NCH) { CP_WAIT(1); } else { CP_WAIT(0); }
        __syncthreads();

        const float* As = smf + (SM_A + (ch & 1) * A_BUF) / 4;
        const float* Bs = smf + (SM_B + (ch & 1) * B_BUF) / 4;

        #pragma unroll
        for (int kc = 0; kc < 4; kc++) {
            const int k0 = kc * 8;
            uint32_t a[2][4];
            #pragma unroll
            for (int mt = 0; mt < 2; mt++) {
                const int r0 = wm * 32 + mt * 16 + g;
                a[mt][0] = rna_tf32(As[(k0 + tig) * A_STR + r0]);
                a[mt][1] = rna_tf32(As[(k0 + tig) * A_STR + r0 + 8]);
                a[mt][2] = rna_tf32(As[(k0 + tig + 4) * A_STR + r0]);
                a[mt][3] = rna_tf32(As[(k0 + tig + 4) * A_STR + r0 + 8]);
            }
            #pragma unroll
            for (int nt = 0; nt < 8; nt++) {
                const int c0 = wn * 64 + nt * 8 + g;
                uint32_t b[2];
                b[0] = __float_as_uint(Bs[c0 * B_STR + k0 + tig]);
                b[1] = __float_as_uint(Bs[c0 * B_STR + k0 + tig + 4]);
                mma8(acc[0][nt], a[0], b);
                mma8(acc[1][nt], a[1], b);
            }
        }
        __syncthreads();   // safe to overwrite this buffer next iteration
    }

    // ---- stage accumulators: S[gate_col][m], stride 132 (conflict-free) ----
    float* S = smf + SM_S / 4;
    #pragma unroll
    for (int mt = 0; mt < 2; mt++) {
        const int r0 = wm * 32 + mt * 16 + g;
        #pragma unroll
        for (int nt = 0; nt < 8; nt++) {
            const int c0 = wn * 64 + nt * 8 + 2 * tig;
            S[(c0    ) * S_STR + r0    ] = acc[mt][nt][0];
            S[(c0 + 1) * S_STR + r0    ] = acc[mt][nt][1];
            S[(c0    ) * S_STR + r0 + 8] = acc[mt][nt][2];
            S[(c0 + 1) * S_STR + r0 + 8] = acc[mt][nt][3];
        }
    }
    __syncthreads();

    // ---- cell update: coalesced over m; 32 units per CTA ----
    float* H2 = smf + SM_H2 / 4;
    const float* bs = smf + SM_BIAS / 4;
    const int m    = tid & 127;
    const int half = tid >> 7;           // 2 units per iteration
    #pragma unroll 4
    for (int it = 0; it < 16; it++) {
        const int u = it * 2 + half;
        float gi = S[(4 * u + 0) * S_STR + m] + bs[4 * u + 0];
        float gf = S[(4 * u + 1) * S_STR + m] + bs[4 * u + 1];
        float gg = S[(4 * u + 2) * S_STR + m] + bs[4 * u + 2];
        float go = S[(4 * u + 3) * S_STR + m] + bs[4 * u + 3];
        const size_t ci = (size_t)(j * 32 + u) * NB + n0 + m;
        float cold = g_Cbuf[ci];
        float cn = sigf(gf) * cold + sigf(gi) * tanhf_(gg);
        g_Cbuf[ci] = cn;
        float hv = sigf(go) * tanhf_(cn);
        hnext[ci] = hv;                   // h-major state, coalesced
        H2[u * H_STR + m] = hv;           // for transposed output store
    }
    __syncthreads();

    // ---- output: out[n][t][h], 128B contiguous stores over the 32-unit tile
    #pragma unroll 4
    for (int i = 0; i < 16; i++) {
        const int mr = wid * 16 + i;
        out[(size_t)(n0 + mr) * TOUT * HD + (size_t)t_out * HD + j * 32 + lane] =
            H2[lane * H_STR + mr];
    }
}

// ---------------------------------------------------------------------------
// launch: prep + 60 steps (K=256) + 54 autoregressive steps (K=128)
// ---------------------------------------------------------------------------
extern "C" void kernel_launch(void* const* d_in, const int* in_sizes, int n_in,
                              void* d_out, int out_size) {
    const float* img = (const float*)d_in[0];
    const float* Wih = (const float*)d_in[2];
    const float* Whh = (const float*)d_in[3];
    const float* bih = (const float*)d_in[4];
    const float* bhh = (const float*)d_in[5];
    float* out = (float*)d_out;

    const int T    = in_sizes[0] / (HD * NB);       // 60
    const int TOUT = out_size / (NB * HD);          // 114

    void *h0p, *h1p;
    cudaGetSymbolAddress(&h0p, g_Hbuf0);
    cudaGetSymbolAddress(&h1p, g_Hbuf1);
    float* hb[2] = {(float*)h0p, (float*)h1p};

    cudaFuncSetAttribute((const void*)lstm_step<8>,
                         cudaFuncAttributeMaxDynamicSharedMemorySize, SM_TOT);
    cudaFuncSetAttribute((const void*)lstm_step<4>,
                         cudaFuncAttributeMaxDynamicSharedMemorySize, SM_TOT);

    prep_kernel<<<512, 256>>>(Wih, Whh, bih, bhh);

    dim3 grid(4, NB / 128);
    for (int t = 0; t < TOUT; t++) {
        float* hp = hb[t & 1];
        float* hn = hb[(t + 1) & 1];
        if (t < T) {
            lstm_step<8><<<grid, 256, SM_TOT>>>(
                img + (size_t)t * HD * NB, hp, hn, out, t, TOUT);
        } else {
            lstm_step<4><<<grid, 256, SM_TOT>>>(
                nullptr, hp, hn, out, t, TOUT);
        }
    }
}